// round 2
// baseline (speedup 1.0000x reference)
#include <cuda_runtime.h>
#include <cuda_bf16.h>

#define KDIM 256
#define TEMPF 1.0e8f
#define ROWS_PER_BLOCK 8   // blockDim = 256 -> 8 warps, 1 row per warp

// Correctly-rounded (to ~2^-39 before final rounding) float exp for r in [-80, 0].
// Range reduction: r = (32m + j)*ln2/32 + f, |f| <= ln2/64.
// exp(r) = 2^m * 2^(j/32) * e^f, with e^f via degree-4 Taylor in double.
__device__ __forceinline__ float exp_cr(float r, const double* __restrict__ T)
{
    float nf = rintf(r * 46.166241f);                 // r * 32/ln2
    int n2 = (int)nf;                                 // <= 0
    int m  = n2 >> 5;                                 // floor(n2/32)
    int j  = n2 & 31;
    double fd = fma((double)nf, -2.1660849392498290e-2, (double)r);  // ln2/32
    double p  = fma(fd, 1.0 / 24.0, 1.0 / 6.0);
    p = fma(fd, p, 0.5);
    p = fma(fd, p, 1.0);
    p = fma(fd, p, 1.0);                              // 1+f+f^2/2+f^3/6+f^4/24
    float sf = (float)(T[j] * p);                     // CR rounding happens here
    return sf * __int_as_float((m + 127) << 23);      // exact power-of-2 scale
}

__global__ __launch_bounds__(256) void quantizer_kernel(
    const float* __restrict__ x,      // (rows) flattened (1024,512)
    const float* __restrict__ cb,     // (256)
    float* __restrict__ soft,         // (rows, 256)
    float* __restrict__ hard,         // (rows, 256)
    float* __restrict__ quant,        // (rows)
    int rows)
{
    // Codebook in shared, PERMUTED so each lane's 8 entries are at stride-32
    // (conflict-free LDS): scb[j*32 + lane] = cb[k(j,lane)]
    __shared__ float  scb[KDIM];
    __shared__ double Texp[32];       // 2^(j/32), j = 0..31
    {
        int k = threadIdx.x;
        float v = cb[k];
        int j, l;
        if (k < 128) { j = (k & 3);             l = (k >> 2); }
        else         { j = 4 + ((k - 128) & 3); l = ((k - 128) >> 2); }
        scb[j * 32 + l] = v;
        if (k < 32) Texp[k] = exp2((double)k * 0.03125);
    }
    __syncthreads();

    const int lane = threadIdx.x & 31;
    const int warp = threadIdx.x >> 5;
    const int row  = blockIdx.x * ROWS_PER_BLOCK + warp;
    if (row >= rows) return;

    // Lane-owned codebook slice + global k indices
    float cbv[8];
    int   kk[8];
#pragma unroll
    for (int j = 0; j < 8; j++) {
        cbv[j] = scb[j * 32 + lane];
        kk[j]  = (j < 4) ? (4 * lane + j) : (128 + 4 * lane + (j - 4));
    }

    const float xv = __ldg(x + row);

    // Pass A: a_k = |x - c_k| (exact; == sqrt((x-c)^2) in RN), find min over row
    float a[8];
    float amin = 3.0e38f;
#pragma unroll
    for (int j = 0; j < 8; j++) {
        a[j] = fabsf(xv - cbv[j]);
        amin = fminf(amin, a[j]);
    }
#pragma unroll
    for (int off = 16; off; off >>= 1)
        amin = fminf(amin, __shfl_xor_sync(0xFFFFFFFFu, amin, off));

    // Window: only entries with t = 1e8*(d_k - d_max) >= -104 can produce a
    // nonzero soft value. d_k >= d_max - 1.04e-6  <=>  a_k <= amin + ~1.04e-6/d_max.
    const float d_est = __expf(-amin);
    const float wthr  = amin + 1.3e-6f / d_est;     // conservative margin

    // Pass B: accurate d only inside the window (warp-uniform skip otherwise)
    float d[8];
#pragma unroll
    for (int j = 0; j < 8; j++) {
        bool on = (a[j] <= wthr);
        float e = 0.0f;
        if (__any_sync(0xFFFFFFFFu, on))
            e = exp_cr(-a[j], Texp);
        d[j] = on ? e : 0.0f;
    }

    // argmax over d with lowest-index tie-break (matches jnp.argmax).
    // Non-window entries have d=0 and are strictly below d_max (>= 1.8e-3).
    float bd = d[0]; int bk = kk[0];
#pragma unroll
    for (int j = 1; j < 8; j++)
        if (d[j] > bd) { bd = d[j]; bk = kk[j]; }   // in-lane k increases with j
#pragma unroll
    for (int off = 16; off; off >>= 1) {
        float od = __shfl_xor_sync(0xFFFFFFFFu, bd, off);
        int   ok = __shfl_xor_sync(0xFFFFFFFFu, bk, off);
        if (od > bd || (od == bd && ok < bk)) { bd = od; bk = ok; }
    }

    // softmax(TEMP * d): scale-then-subtract exactly like jax.nn.softmax.
    // __fmul_rn/__fadd_rn block FMA contraction. For windowed-out entries
    // (d=0), t = -amax <= -1.8e5 so __expf(t) == 0 exactly.
    const float amax = __fmul_rn(TEMPF, bd);
    float s[8];
    float sum = 0.0f, qp = 0.0f;
#pragma unroll
    for (int j = 0; j < 8; j++) {
        float t = __fadd_rn(__fmul_rn(TEMPF, d[j]), -amax);  // exact grid diff
        s[j] = __expf(t);     // 2-ulp rel error on O(1) entries: negligible
        sum += s[j];
        qp  = __fmaf_rn(s[j], cbv[j], qp);
    }
#pragma unroll
    for (int off = 16; off; off >>= 1) {
        sum += __shfl_xor_sync(0xFFFFFFFFu, sum, off);
        qp  += __shfl_xor_sync(0xFFFFFFFFu, qp,  off);
    }
    const float inv = 1.0f / sum;

    // Coalesced writes: each warp-store covers 512 contiguous bytes (STG.128)
    const size_t base = (size_t)row * KDIM;
    float4 sv0 = make_float4(s[0] * inv, s[1] * inv, s[2] * inv, s[3] * inv);
    float4 sv1 = make_float4(s[4] * inv, s[5] * inv, s[6] * inv, s[7] * inv);
    *reinterpret_cast<float4*>(soft + base +       4 * lane) = sv0;
    *reinterpret_cast<float4*>(soft + base + 128 + 4 * lane) = sv1;

    float4 hv0 = make_float4(kk[0] == bk ? 1.0f : 0.0f,
                             kk[1] == bk ? 1.0f : 0.0f,
                             kk[2] == bk ? 1.0f : 0.0f,
                             kk[3] == bk ? 1.0f : 0.0f);
    float4 hv1 = make_float4(kk[4] == bk ? 1.0f : 0.0f,
                             kk[5] == bk ? 1.0f : 0.0f,
                             kk[6] == bk ? 1.0f : 0.0f,
                             kk[7] == bk ? 1.0f : 0.0f);
    *reinterpret_cast<float4*>(hard + base +       4 * lane) = hv0;
    *reinterpret_cast<float4*>(hard + base + 128 + 4 * lane) = hv1;

    if (lane == 0) quant[row] = qp * inv;
}

extern "C" void kernel_launch(void* const* d_in, const int* in_sizes, int n_in,
                              void* d_out, int out_size)
{
    const float* x  = (const float*)d_in[0];   // inputs (1024,512) f32
    const float* cb = (const float*)d_in[1];   // codebook (1,256) f32
    const int rows  = in_sizes[0];             // 524288

    float* out   = (float*)d_out;              // [soft | hard | quantized]
    float* soft  = out;
    float* hard  = out + (size_t)rows * KDIM;
    float* quant = out + 2ull * (size_t)rows * KDIM;

    const int blocks = (rows + ROWS_PER_BLOCK - 1) / ROWS_PER_BLOCK;
    quantizer_kernel<<<blocks, 256>>>(x, cb, soft, hard, quant, rows);
}

// round 3
// speedup vs baseline: 2.1776x; 2.1776x over previous
#include <cuda_runtime.h>
#include <cuda_bf16.h>

#define KDIM 256
#define TEMPF 1.0e8f
#define RPB 256          // rows per block (1 thread per row in phase 1)
#define MAXC 8           // max window candidates per row (P(overflow) ~ 1e-13/row)

// Correctly-rounded (to ~2^-39 before final rounding) float exp for r in [-80, 0].
__device__ __forceinline__ float exp_cr(float r, const double* __restrict__ T)
{
    float nf = rintf(r * 46.166241f);                 // r * 32/ln2
    int n2 = (int)nf;
    int m  = n2 >> 5;
    int j  = n2 & 31;
    double fd = fma((double)nf, -2.1660849392498290e-2, (double)r);  // r - nf*ln2/32
    double p  = fma(fd, 1.0 / 24.0, 1.0 / 6.0);
    p = fma(fd, p, 0.5);
    p = fma(fd, p, 1.0);
    p = fma(fd, p, 1.0);
    float sf = (float)(T[j] * p);
    return sf * __int_as_float((m + 127) << 23);
}

__global__ __launch_bounds__(256, 4) void quantizer_kernel(
    const float* __restrict__ x,      // (rows)
    const float* __restrict__ cb,     // (256)
    float* __restrict__ soft,         // (rows, 256)
    float* __restrict__ hard,         // (rows, 256)
    float* __restrict__ quant,        // (rows)
    int rows)
{
    __shared__ float4 scb4[64];                 // codebook, natural order
    __shared__ double Texp[32];                 // 2^(j/32)
    __shared__ int    s_bk[RPB];
    __shared__ int    s_n [RPB];
    __shared__ short  s_idx[RPB][MAXC];
    __shared__ float  s_val[RPB][MAXC];

    const int tid = threadIdx.x;
    if (tid < 64) scb4[tid] = reinterpret_cast<const float4*>(cb)[tid];
    if (tid < 32) Texp[tid] = exp2((double)tid * 0.03125);
    __syncthreads();

    const int row0 = blockIdx.x * RPB;
    const int row  = row0 + tid;

    // ---------------- Phase 1: thread-per-row sparse compute ----------------
    if (row < rows) {
        const float xv = x[row];

        // pass 1: amin over 256 entries (4 independent min chains for ILP)
        float m0 = 3.0e38f, m1 = 3.0e38f, m2 = 3.0e38f, m3 = 3.0e38f;
#pragma unroll 16
        for (int i = 0; i < 64; i++) {
            float4 c = scb4[i];
            m0 = fminf(m0, fabsf(xv - c.x));
            m1 = fminf(m1, fabsf(xv - c.y));
            m2 = fminf(m2, fabsf(xv - c.z));
            m3 = fminf(m3, fabsf(xv - c.w));
        }
        const float amin = fminf(fminf(m0, m1), fminf(m2, m3));

        // window: entries with t = 1e8*(d-dmax) >= -104 can be nonzero
        const float d_est = __expf(-amin);
        const float wthr  = amin + 1.3e-6f / d_est;

        // pass 2: capture candidates (typically 1-2)
        int   nc = 0;
        short idxs[MAXC];
        float avs[MAXC], cvs[MAXC];
#pragma unroll 8
        for (int i = 0; i < 64; i++) {
            float4 c = scb4[i];
            float a0 = fabsf(xv - c.x);
            float a1 = fabsf(xv - c.y);
            float a2 = fabsf(xv - c.z);
            float a3 = fabsf(xv - c.w);
            if (a0 <= wthr && nc < MAXC) { idxs[nc] = (short)(4*i+0); avs[nc] = a0; cvs[nc] = c.x; nc++; }
            if (a1 <= wthr && nc < MAXC) { idxs[nc] = (short)(4*i+1); avs[nc] = a1; cvs[nc] = c.y; nc++; }
            if (a2 <= wthr && nc < MAXC) { idxs[nc] = (short)(4*i+2); avs[nc] = a2; cvs[nc] = c.z; nc++; }
            if (a3 <= wthr && nc < MAXC) { idxs[nc] = (short)(4*i+3); avs[nc] = a3; cvs[nc] = c.w; nc++; }
        }

        // accurate d on candidates; argmax with lowest-index tie-break
        float dcand[MAXC];
        float bd = -1.0f; int bk = 0;
        for (int i = 0; i < nc; i++) {
            float di = exp_cr(-avs[i], Texp);
            dcand[i] = di;
            if (di > bd) { bd = di; bk = idxs[i]; }   // ascending k -> first-index ties
        }

        // softmax(TEMP*d), scale-then-subtract exactly like jax.nn.softmax.
        // Non-candidates have d=0 -> t = -amax <= -2.5e5 -> exp == 0 exactly.
        const float amax = __fmul_rn(TEMPF, bd);
        float sum = 0.0f, qp = 0.0f;
        float sv[MAXC];
        for (int i = 0; i < nc; i++) {
            float t = __fadd_rn(__fmul_rn(TEMPF, dcand[i]), -amax);
            float s = __expf(t);
            sv[i] = s;
            sum += s;
            qp  = __fmaf_rn(s, cvs[i], qp);
        }
        const float inv = 1.0f / sum;
        quant[row] = qp * inv;                       // coalesced across threads

        s_bk[tid] = bk;
        s_n [tid] = nc;
        for (int i = 0; i < nc; i++) {
            s_idx[tid][i] = idxs[i];
            s_val[tid][i] = sv[i] * inv;
        }
    } else {
        s_n[tid] = 0; s_bk[tid] = -1;
    }
    __syncthreads();

    // ---------------- Phase 2: warp-per-row dense streaming stores ----------------
    const int lane = tid & 31;
    const int warp = tid >> 5;
    const int k0 = 4 * lane;          // entries k0..k0+3
    const int k1 = 128 + 4 * lane;    // entries k1..k1+3

    for (int rr = warp; rr < RPB; rr += 8) {
        const int grow = row0 + rr;
        if (grow >= rows) break;
        const int n  = s_n[rr];
        const int bk = s_bk[rr];
        const size_t base = (size_t)grow * KDIM;

        float4 sv0 = make_float4(0.f, 0.f, 0.f, 0.f);
        float4 sv1 = make_float4(0.f, 0.f, 0.f, 0.f);
        for (int i = 0; i < n; i++) {
            const int   ki = s_idx[rr][i];     // LDS broadcast
            const float vi = s_val[rr][i];
            sv0.x = (ki == k0    ) ? vi : sv0.x;
            sv0.y = (ki == k0 + 1) ? vi : sv0.y;
            sv0.z = (ki == k0 + 2) ? vi : sv0.z;
            sv0.w = (ki == k0 + 3) ? vi : sv0.w;
            sv1.x = (ki == k1    ) ? vi : sv1.x;
            sv1.y = (ki == k1 + 1) ? vi : sv1.y;
            sv1.z = (ki == k1 + 2) ? vi : sv1.z;
            sv1.w = (ki == k1 + 3) ? vi : sv1.w;
        }
        float4 hv0 = make_float4(bk == k0     ? 1.f : 0.f,
                                 bk == k0 + 1 ? 1.f : 0.f,
                                 bk == k0 + 2 ? 1.f : 0.f,
                                 bk == k0 + 3 ? 1.f : 0.f);
        float4 hv1 = make_float4(bk == k1     ? 1.f : 0.f,
                                 bk == k1 + 1 ? 1.f : 0.f,
                                 bk == k1 + 2 ? 1.f : 0.f,
                                 bk == k1 + 3 ? 1.f : 0.f);

        reinterpret_cast<float4*>(soft + base)[lane]       = sv0;
        reinterpret_cast<float4*>(soft + base + 128)[lane] = sv1;
        reinterpret_cast<float4*>(hard + base)[lane]       = hv0;
        reinterpret_cast<float4*>(hard + base + 128)[lane] = hv1;
    }
}

extern "C" void kernel_launch(void* const* d_in, const int* in_sizes, int n_in,
                              void* d_out, int out_size)
{
    const float* x  = (const float*)d_in[0];   // inputs (1024,512) f32
    const float* cb = (const float*)d_in[1];   // codebook (1,256) f32
    const int rows  = in_sizes[0];             // 524288

    float* out   = (float*)d_out;              // [soft | hard | quantized]
    float* soft  = out;
    float* hard  = out + (size_t)rows * KDIM;
    float* quant = out + 2ull * (size_t)rows * KDIM;

    const int blocks = (rows + RPB - 1) / RPB;
    quantizer_kernel<<<blocks, 256>>>(x, cb, soft, hard, quant, rows);
}